// round 6
// baseline (speedup 1.0000x reference)
#include <cuda_runtime.h>

// Shapes (fixed):
//   p1: [6,256,256] f32   bank
//   p2: [131072,256] f32  table
//   p3: [6,1] i32         row ids into p2
//   p4: [1,256] i32       gather columns
//   p5: [6,1] i32         slot (c index) per batch
//   p6: [1,256] i32       scatter columns
//   p7: [6,256,256] f32   EMA state
//   p8: [12,6,256] f32    query features
// out1: [12,6,256] f32, out2: [6,256,256] f32 (concatenated in d_out)

#define B 6
#define S 256
#define D 256
#define A 12
#define ABD (A * B * D)  // 18432

// Role A tiling (out2): 16c x 64d tiles, grid 4*6*16 = 384 blocks.
#define CS_A 16
#define CLEN 16
#define DT 64
// Role B tiling (out1): one block per (b, 16-d chunk) = 6*16 = 96 blocks.
#define NB_B (B * 16)
#define NB_A (4 * B * CS_A)

// Single kernel, two independent roles selected by blockIdx.x.
//   Role B (ids 0..95):   out1[a,b,d] = sum_c p8[a,b,c] * add[b,c,d], add recomputed.
//   Role A (ids 96..479): out2[b,d,c] = add[b,c,d] via smem transpose.
// No inter-block dependencies; all reduction orders fixed -> deterministic.
__global__ __launch_bounds__(256)
void fused_kernel(const float* __restrict__ p1,
                  const float* __restrict__ p2,
                  const int* __restrict__ p3,
                  const int* __restrict__ p4,
                  const int* __restrict__ p5,
                  const int* __restrict__ p6,
                  const float* __restrict__ p7,
                  const float* __restrict__ p8,
                  float* __restrict__ out1,
                  float* __restrict__ out2) {
    __shared__ float  p8sA[A * CLEN];      // role A: p8 slice (768 B)
    __shared__ float4 g4[DT / 4];          // scattered-row slice (role A: 64d, role B: 16d)
    __shared__ float  s[CLEN][DT + 4];     // role A transpose tile
    __shared__ float  p8sB[A * 256];       // role B: full p8[:,b,:] (12 KB)
    __shared__ float4 red[8 * A * 4];      // role B cross-warp reduction (6 KB)

    const int id = blockIdx.x;
    const int t  = threadIdx.x;

    if (id < NB_B) {
        // ── Role B: out1 ────────────────────────────────────────────────
        const int b  = id / 16;
        const int d0 = (id % 16) * 16;
        const int slot = p5[b];

        for (int i = t; i < A * 256; i += 256) {
            int a = i >> 8, c = i & 255;
            p8sB[i] = p8[(a * B + b) * 256 + c];
        }
        if (t < 4) g4[t] = ((const float4*)(p1 + (b * S + slot) * D + d0))[t];
        __syncthreads();
        {
            int col = p6[t];
            if (col >= d0 && col < d0 + 16)
                ((float*)g4)[col - d0] = p2[(long long)p3[b] * D + p4[t]];
        }
        __syncthreads();

        const float* p1b = p1 + b * (S * D);
        const float* p7b = p7 + b * (S * D);
        const int tx = t & 3;          // f4 lane over 16 d
        const int ty = t >> 2;         // 64 parallel c

        float4 acc[A];
        #pragma unroll
        for (int a = 0; a < A; a++) acc[a] = make_float4(0.f, 0.f, 0.f, 0.f);

        #pragma unroll
        for (int i = 0; i < 4; i++) {
            int c = ty + 64 * i;       // fixed ascending order per thread
            float4 v1 = ((const float4*)(p1b + c * D + d0))[tx];
            float4 v7 = ((const float4*)(p7b + c * D + d0))[tx];
            float4 bse = (c == slot) ? g4[tx] : v1;
            float4 val;
            val.x = fmaf(0.975f, v7.x, bse.x);
            val.y = fmaf(0.975f, v7.y, bse.y);
            val.z = fmaf(0.975f, v7.z, bse.z);
            val.w = fmaf(0.975f, v7.w, bse.w);
            #pragma unroll
            for (int a = 0; a < A; a++) {
                float w = p8sB[a * 256 + c];
                acc[a].x = fmaf(w, val.x, acc[a].x);
                acc[a].y = fmaf(w, val.y, acc[a].y);
                acc[a].z = fmaf(w, val.z, acc[a].z);
                acc[a].w = fmaf(w, val.w, acc[a].w);
            }
        }

        // Butterfly over the 8 c-groups within each warp (fixed order).
        #pragma unroll
        for (int off = 4; off <= 16; off <<= 1) {
            #pragma unroll
            for (int a = 0; a < A; a++) {
                acc[a].x += __shfl_xor_sync(0xffffffffu, acc[a].x, off);
                acc[a].y += __shfl_xor_sync(0xffffffffu, acc[a].y, off);
                acc[a].z += __shfl_xor_sync(0xffffffffu, acc[a].z, off);
                acc[a].w += __shfl_xor_sync(0xffffffffu, acc[a].w, off);
            }
        }
        const int lane = t & 31, w = t >> 5;
        if (lane < 4) {
            #pragma unroll
            for (int a = 0; a < A; a++) red[(w * A + a) * 4 + lane] = acc[a];
        }
        __syncthreads();
        if (t < A * 4) {
            int a = t >> 2, txo = t & 3;
            float4 sum = red[(0 * A + a) * 4 + txo];
            #pragma unroll
            for (int q = 1; q < 8; q++) {           // fixed warp order
                float4 p = red[(q * A + a) * 4 + txo];
                sum.x += p.x; sum.y += p.y; sum.z += p.z; sum.w += p.w;
            }
            ((float4*)out1)[(((a * B + b) * 256) + d0) / 4 + txo] = sum;
        }
        return;
    }

    // ── Role A: out2 ────────────────────────────────────────────────────
    const int k  = id - NB_B;
    const int d0 = (k & 3) * DT;
    const int b  = (k >> 2) % B;
    const int cs = k / (4 * B);
    const int c0 = cs * CLEN;
    const int slot = p5[b];

    if (t < A * CLEN) {
        int a = t >> 4, cl = t & 15;
        p8sA[t] = p8[(a * B + b) * 256 + c0 + cl];   // kept for symmetry; unused
    }
    if (t < DT / 4)
        g4[t] = ((const float4*)(p1 + (b * S + slot) * D + d0))[t];
    __syncthreads();
    {
        int col = p6[t];
        if (col >= d0 && col < d0 + DT)
            ((float*)g4)[col - d0] = p2[(long long)p3[b] * D + p4[t]];
    }
    __syncthreads();

    const float* p1b = p1 + b * (S * D);
    const float* p7b = p7 + b * (S * D);
    float* out2b = out2 + b * (S * D);

    const int tx = t & 15;
    const int ty = t >> 4;
    const int c  = c0 + ty;
    float4 v1 = ((const float4*)(p1b + c * D + d0))[tx];
    float4 v7 = ((const float4*)(p7b + c * D + d0))[tx];
    float4 bse = (c == slot) ? g4[tx] : v1;
    float4 val;
    val.x = fmaf(0.975f, v7.x, bse.x);
    val.y = fmaf(0.975f, v7.y, bse.y);
    val.z = fmaf(0.975f, v7.z, bse.z);
    val.w = fmaf(0.975f, v7.w, bse.w);
    ((float4*)&s[ty][0])[tx] = val;
    __syncthreads();

    {
        int cl  = t & 15;
        int dl0 = t >> 4;
        #pragma unroll
        for (int p = 0; p < 4; p++) {
            int dl = dl0 + p * 16;
            out2b[(d0 + dl) * D + c0 + cl] = s[cl][dl];
        }
    }
}

extern "C" void kernel_launch(void* const* d_in, const int* in_sizes, int n_in,
                              void* d_out, int out_size) {
    const float* p1 = (const float*)d_in[0];
    const float* p2 = (const float*)d_in[1];
    const int*   p3 = (const int*)d_in[2];
    const int*   p4 = (const int*)d_in[3];
    const int*   p5 = (const int*)d_in[4];
    const int*   p6 = (const int*)d_in[5];
    const float* p7 = (const float*)d_in[6];
    const float* p8 = (const float*)d_in[7];

    float* out1 = (float*)d_out;                 // [12,6,256]
    float* out2 = out1 + ABD;                    // [6,256,256]

    fused_kernel<<<NB_A + NB_B, 256>>>(p1, p2, p3, p4, p5, p6, p7, p8, out1, out2);
}

// round 7
// speedup vs baseline: 1.2490x; 1.2490x over previous
#include <cuda_runtime.h>

// Shapes (fixed):
//   p1: [6,256,256] f32   bank
//   p2: [131072,256] f32  table
//   p3: [6,1] i32         row ids into p2
//   p4: [1,256] i32       gather columns
//   p5: [6,1] i32         slot (c index) per batch
//   p6: [1,256] i32       scatter columns
//   p7: [6,256,256] f32   EMA state
//   p8: [12,6,256] f32    query features
// out1: [12,6,256] f32, out2: [6,256,256] f32 (concatenated in d_out)

#define B 6
#define S 256
#define D 256
#define A 12
#define ABD (A * B * D)  // 18432

// Role B (out1): one block per (b, 32-d chunk): 6*8 = 48 blocks.
#define NB_B (B * 8)
// Role A (out2): 16c x 64d tiles: 4 * 6 * 16 = 384 blocks.
#define CS_A 16
#define CLEN 16
#define DT 64
#define NB_A (4 * B * CS_A)

// Shared pool (floats), unioned across roles:
//  role B: sB[256][34] (8704) | p8s[12][256] (3072) | gB[32]  -> 11808 floats
//  role A: sA[16][68] (1088)  | gA[64] at +1088
#define POOL_FLOATS 11808

__global__ __launch_bounds__(256)
void fused_kernel(const float* __restrict__ p1,
                  const float* __restrict__ p2,
                  const int* __restrict__ p3,
                  const int* __restrict__ p4,
                  const int* __restrict__ p5,
                  const int* __restrict__ p6,
                  const float* __restrict__ p7,
                  const float* __restrict__ p8,
                  float* __restrict__ out1,
                  float* __restrict__ out2) {
    __shared__ __align__(16) float pool[POOL_FLOATS];
    const int id = blockIdx.x;
    const int t  = threadIdx.x;

    if (id < NB_B) {
        // ── Role B: out1 via smem-tile micro-GEMM ───────────────────────
        float* sB  = pool;               // [256][34] add tile (c-major)
        float* p8s = pool + 256 * 34;    // [12][256]
        float* g   = pool + 256 * 34 + A * 256;  // [32] scattered-row slice

        const int b    = id >> 3;
        const int d0   = (id & 7) * 32;
        const int slot = p5[b];

        // Stage p8 (a = i, c = t) and scattered-row base.
        #pragma unroll
        for (int i = 0; i < A; i++)
            p8s[i * 256 + t] = p8[(i * B + b) * 256 + t];
        if (t < 8)
            ((float4*)g)[t] = ((const float4*)(p1 + (b * S + slot) * D + d0))[t];
        __syncthreads();
        {
            int col = p6[t];
            if (col >= d0 && col < d0 + 32)
                g[col - d0] = p2[(long long)p3[b] * D + p4[t]];
        }
        __syncthreads();

        // Build add tile: thread = (f4 d-lane fl, c-row cr), 8 c-iterations.
        const float* p1b = p1 + b * (S * D);
        const float* p7b = p7 + b * (S * D);
        const int fl = t & 7, cr = t >> 3;
        #pragma unroll
        for (int i = 0; i < 8; i++) {
            int c = cr + 32 * i;
            float4 v1 = ((const float4*)(p1b + c * D + d0))[fl];
            float4 v7 = ((const float4*)(p7b + c * D + d0))[fl];
            float4 bs = (c == slot) ? ((const float4*)g)[fl] : v1;
            float* row = sB + c * 34 + fl * 4;
            row[0] = fmaf(0.975f, v7.x, bs.x);
            row[1] = fmaf(0.975f, v7.y, bs.y);
            row[2] = fmaf(0.975f, v7.z, bs.z);
            row[3] = fmaf(0.975f, v7.w, bs.w);
        }
        __syncthreads();

        // Micro-GEMM: 192 threads, each owns (a, d-pair); fixed 256-c order.
        if (t < A * 16) {
            const int a  = t >> 4;
            const int dp = t & 15;
            const float* pr = p8s + a * 256;
            const float* sc = sB + dp * 2;
            float ax = 0.f, ay = 0.f;
            #pragma unroll 8
            for (int c = 0; c < 256; c++) {
                float2 v = *(const float2*)(sc + c * 34);
                float w  = pr[c];
                ax = fmaf(w, v.x, ax);
                ay = fmaf(w, v.y, ay);
            }
            int base = (a * B + b) * 256 + d0 + dp * 2;
            out1[base]     = ax;
            out1[base + 1] = ay;
        }
        return;
    }

    // ── Role A: out2 via transpose tile ─────────────────────────────────
    float* sA = pool;            // [16][68]
    float* gA = pool + 1088;     // [64], 16B-aligned

    const int k  = id - NB_B;
    const int d0 = (k & 3) * DT;
    const int b  = (k >> 2) % B;
    const int cs = k / (4 * B);
    const int c0 = cs * CLEN;
    const int slot = p5[b];

    if (t < DT / 4)
        ((float4*)gA)[t] = ((const float4*)(p1 + (b * S + slot) * D + d0))[t];
    __syncthreads();
    {
        int col = p6[t];
        if (col >= d0 && col < d0 + DT)
            gA[col - d0] = p2[(long long)p3[b] * D + p4[t]];
    }
    __syncthreads();

    const float* p1b = p1 + b * (S * D);
    const float* p7b = p7 + b * (S * D);
    float* out2b = out2 + b * (S * D);

    const int tx = t & 15;       // f4 d lane (64 d)
    const int ty = t >> 4;       // c lane (16 c)
    const int c  = c0 + ty;
    float4 v1 = ((const float4*)(p1b + c * D + d0))[tx];
    float4 v7 = ((const float4*)(p7b + c * D + d0))[tx];
    float4 bs = (c == slot) ? ((const float4*)gA)[tx] : v1;
    float4 val;
    val.x = fmaf(0.975f, v7.x, bs.x);
    val.y = fmaf(0.975f, v7.y, bs.y);
    val.z = fmaf(0.975f, v7.z, bs.z);
    val.w = fmaf(0.975f, v7.w, bs.w);
    ((float4*)(sA + ty * 68))[tx] = val;
    __syncthreads();

    {
        int cl  = t & 15;
        int dl0 = t >> 4;
        #pragma unroll
        for (int p = 0; p < 4; p++) {
            int dl = dl0 + p * 16;
            out2b[(d0 + dl) * D + c0 + cl] = sA[cl * 68 + dl];
        }
    }
}

extern "C" void kernel_launch(void* const* d_in, const int* in_sizes, int n_in,
                              void* d_out, int out_size) {
    const float* p1 = (const float*)d_in[0];
    const float* p2 = (const float*)d_in[1];
    const int*   p3 = (const int*)d_in[2];
    const int*   p4 = (const int*)d_in[3];
    const int*   p5 = (const int*)d_in[4];
    const int*   p6 = (const int*)d_in[5];
    const float* p7 = (const float*)d_in[6];
    const float* p8 = (const float*)d_in[7];

    float* out1 = (float*)d_out;                 // [12,6,256]
    float* out2 = out1 + ABD;                    // [6,256,256]

    fused_kernel<<<NB_A + NB_B, 256>>>(p1, p2, p3, p4, p5, p6, p7, p8, out1, out2);
}